// round 17
// baseline (speedup 1.0000x reference)
#include <cuda_runtime.h>
#include <cuda_bf16.h>
#include <math.h>

#define E    512
#define HH   1536
#define G4   6144
#define SS   32
#define TT   48
#define NV   128
#define NB   128       // persistent blocks (1/SM)
#define NT   512       // 16 warps
#define UPB  12        // h2/c2 units per block
#define RPB  48        // gate rows / whh1 rows per block
#define KU   3         // h-vector elems per thread (HH/NT)
#define LSTR 64        // logit slot stride (256B)
#define FSTR 32        // flag slot stride (128B)
#define WELEM (G4 * HH)

typedef unsigned long long u64;

// ---------------- persistent device state ----------------
__device__ float          g_xproj[NV * G4];            // W_ih1@emb[v] + b_ih1 + b_hh1
__device__ __nv_bfloat16  g_w2cat[(size_t)G4 * 2 * HH];// [W_ih2 | W_hh2] rows of 3072
__device__ __nv_bfloat16  g_whh1[WELEM];
__device__ float          g_c1[2][HH];
__device__ float          g_c2[HH];
__device__ float          g_h2[2][HH];
__device__ float          g_g1[2][G4];                 // W_hh1 @ h1(t), double buffered
__device__ float          g_log3[3][SS * LSTR];        // triple-buffered padded logits
__device__ unsigned       g_flags[NB * FSTR];          // monotonic epochs (never reset)

__device__ __forceinline__ float fsigm(float x) {
    return __fdividef(1.0f, 1.0f + __expf(-x));
}
__device__ __forceinline__ float ftanh(float x) {
    x = fminf(fmaxf(x, -15.0f), 15.0f);
    float e = __expf(2.0f * x);
    return __fdividef(e - 1.0f, e + 1.0f);
}
__device__ __forceinline__ float warpsum(float v) {
    #pragma unroll
    for (int o = 16; o; o >>= 1) v += __shfl_down_sync(0xffffffffu, v, o);
    return v;
}

// ---- packed f32x2 helpers (sm_100+) ----
__device__ __forceinline__ u64 f2pack(float x, float y) {
    u64 r; asm("mov.b64 %0, {%1, %2};" : "=l"(r) : "f"(x), "f"(y)); return r;
}
__device__ __forceinline__ float f2sum(u64 v) {
    float x, y; asm("mov.b64 {%0, %1}, %2;" : "=f"(x), "=f"(y) : "l"(v));
    return x + y;
}
__device__ __forceinline__ u64 bf2f2(unsigned q) {   // bf16x2 -> (f32,f32)
    unsigned lo = q << 16, hi = q & 0xFFFF0000u;
    u64 r; asm("mov.b64 %0, {%1, %2};" : "=l"(r) : "r"(lo), "r"(hi)); return r;
}
__device__ __forceinline__ u64 ffma2(u64 a, u64 b, u64 c) {
    u64 d; asm("fma.rn.f32x2 %0, %1, %2, %3;" : "=l"(d) : "l"(a), "l"(b), "l"(c));
    return d;
}

// convert 8 fp32 (two float4) -> uint4 of bf16
__device__ __forceinline__ uint4 cvt8(float4 a, float4 c) {
    __nv_bfloat162 q0 = __floats2bfloat162_rn(a.x, a.y);
    __nv_bfloat162 q1 = __floats2bfloat162_rn(a.z, a.w);
    __nv_bfloat162 q2 = __floats2bfloat162_rn(c.x, c.y);
    __nv_bfloat162 q3 = __floats2bfloat162_rn(c.z, c.w);
    uint4 o;
    o.x = *(unsigned*)&q0; o.y = *(unsigned*)&q1;
    o.z = *(unsigned*)&q2; o.w = *(unsigned*)&q3;
    return o;
}

// 3 consecutive rows from one base; one shared vector pass
template<int SEGS>
__device__ __forceinline__ void dot3_acc(const __nv_bfloat16* __restrict__ base,
                                         size_t stride, const float* __restrict__ sv,
                                         int lane, float* acc) {
    u64 p0 = 0ull, p1 = 0ull, p2 = 0ull;
    #pragma unroll
    for (int j = 0; j < SEGS; j++) {
        int seg = lane + 32 * j;
        const float4* v = (const float4*)(sv + seg * 8);
        float4 v0 = v[0], v1 = v[1];
        u64 vx = f2pack(v0.x, v0.y), vy = f2pack(v0.z, v0.w);
        u64 vz = f2pack(v1.x, v1.y), vw = f2pack(v1.z, v1.w);
        uint4 a0 = __ldg((const uint4*)(base) + seg);
        uint4 a1 = __ldg((const uint4*)(base + stride) + seg);
        uint4 a2 = __ldg((const uint4*)(base + 2 * stride) + seg);
        u64 p;
        p = bf2f2(a0.x); p0 = ffma2(p, vx, p0);
        p = bf2f2(a0.y); p0 = ffma2(p, vy, p0);
        p = bf2f2(a0.z); p0 = ffma2(p, vz, p0);
        p = bf2f2(a0.w); p0 = ffma2(p, vw, p0);
        p = bf2f2(a1.x); p1 = ffma2(p, vx, p1);
        p = bf2f2(a1.y); p1 = ffma2(p, vy, p1);
        p = bf2f2(a1.z); p1 = ffma2(p, vz, p1);
        p = bf2f2(a1.w); p1 = ffma2(p, vw, p1);
        p = bf2f2(a2.x); p2 = ffma2(p, vx, p2);
        p = bf2f2(a2.y); p2 = ffma2(p, vy, p2);
        p = bf2f2(a2.z); p2 = ffma2(p, vz, p2);
        p = bf2f2(a2.w); p2 = ffma2(p, vw, p2);
    }
    acc[0] += f2sum(p0);
    acc[1] += f2sum(p1);
    acc[2] += f2sum(p2);
}

// FUSED: 3 rows from baseA + 3 rows from baseB, ONE vector pass
template<int SEGS>
__device__ __forceinline__ void dot3x3_acc(const __nv_bfloat16* __restrict__ baseA,
                                           size_t strideA,
                                           const __nv_bfloat16* __restrict__ baseB,
                                           size_t strideB,
                                           const float* __restrict__ sv, int lane,
                                           float* accA, float* accB) {
    u64 pa0 = 0ull, pa1 = 0ull, pa2 = 0ull;
    u64 pb0 = 0ull, pb1 = 0ull, pb2 = 0ull;
    #pragma unroll
    for (int j = 0; j < SEGS; j++) {
        int seg = lane + 32 * j;
        const float4* v = (const float4*)(sv + seg * 8);
        float4 v0 = v[0], v1 = v[1];
        u64 vx = f2pack(v0.x, v0.y), vy = f2pack(v0.z, v0.w);
        u64 vz = f2pack(v1.x, v1.y), vw = f2pack(v1.z, v1.w);
        uint4 a0 = __ldg((const uint4*)(baseA) + seg);
        uint4 a1 = __ldg((const uint4*)(baseA + strideA) + seg);
        uint4 a2 = __ldg((const uint4*)(baseA + 2 * strideA) + seg);
        uint4 b0 = __ldg((const uint4*)(baseB) + seg);
        uint4 b1 = __ldg((const uint4*)(baseB + strideB) + seg);
        uint4 b2 = __ldg((const uint4*)(baseB + 2 * strideB) + seg);
        u64 p;
        p = bf2f2(a0.x); pa0 = ffma2(p, vx, pa0);
        p = bf2f2(a0.y); pa0 = ffma2(p, vy, pa0);
        p = bf2f2(a0.z); pa0 = ffma2(p, vz, pa0);
        p = bf2f2(a0.w); pa0 = ffma2(p, vw, pa0);
        p = bf2f2(a1.x); pa1 = ffma2(p, vx, pa1);
        p = bf2f2(a1.y); pa1 = ffma2(p, vy, pa1);
        p = bf2f2(a1.z); pa1 = ffma2(p, vz, pa1);
        p = bf2f2(a1.w); pa1 = ffma2(p, vw, pa1);
        p = bf2f2(a2.x); pa2 = ffma2(p, vx, pa2);
        p = bf2f2(a2.y); pa2 = ffma2(p, vy, pa2);
        p = bf2f2(a2.z); pa2 = ffma2(p, vz, pa2);
        p = bf2f2(a2.w); pa2 = ffma2(p, vw, pa2);
        p = bf2f2(b0.x); pb0 = ffma2(p, vx, pb0);
        p = bf2f2(b0.y); pb0 = ffma2(p, vy, pb0);
        p = bf2f2(b0.z); pb0 = ffma2(p, vz, pb0);
        p = bf2f2(b0.w); pb0 = ffma2(p, vw, pb0);
        p = bf2f2(b1.x); pb1 = ffma2(p, vx, pb1);
        p = bf2f2(b1.y); pb1 = ffma2(p, vy, pb1);
        p = bf2f2(b1.z); pb1 = ffma2(p, vz, pb1);
        p = bf2f2(b1.w); pb1 = ffma2(p, vw, pb1);
        p = bf2f2(b2.x); pb2 = ffma2(p, vx, pb2);
        p = bf2f2(b2.y); pb2 = ffma2(p, vy, pb2);
        p = bf2f2(b2.z); pb2 = ffma2(p, vz, pb2);
        p = bf2f2(b2.w); pb2 = ffma2(p, vw, pb2);
    }
    accA[0] += f2sum(pa0);
    accA[1] += f2sum(pa1);
    accA[2] += f2sum(pa2);
    accB[0] += f2sum(pb0);
    accB[1] += f2sum(pb1);
    accB[2] += f2sum(pb2);
}

// symmetric grid barrier: padded per-block flags, first NB threads poll
__device__ __forceinline__ void grid_sync(int b, unsigned ep) {
    __threadfence();
    __syncthreads();
    if (threadIdx.x == 0)
        *(volatile unsigned*)&g_flags[b * FSTR] = ep;
    if (threadIdx.x < NB) {
        volatile unsigned* f = &g_flags[threadIdx.x * FSTR];
        while ((int)(*f - ep) < 0) { __nanosleep(32); }
    }
    __syncthreads();
    __threadfence();
}

// ================== the one and only kernel ==================
__global__ void __launch_bounds__(NT, 1)
nas_all(const int*   __restrict__ input_id,
        const float* __restrict__ emb,
        const float* __restrict__ Wih1,
        const float* __restrict__ Whh1f,
        const float* __restrict__ bih1, const float* __restrict__ bhh1,
        const float* __restrict__ Wih2f,
        const float* __restrict__ Whh2f,
        const float* __restrict__ bih2, const float* __restrict__ bhh2,
        const float* __restrict__ Wout,
        const float* __restrict__ bout,
        float* __restrict__ out) {
    __shared__ __align__(16) float sMem[16 * (E + 8)];   // 33.3 KB; aliased
    float* sV  = sMem;                        // loop: [h1 ; h2] (3072)
    float* sWo = sMem + 2 * HH;               // loop: head slice (384)
    float* sG  = sMem + 2 * HH + SS * UPB;    // loop: gates (48)
    __shared__ unsigned sBase;

    const int tid  = threadIdx.x;
    const int w    = tid >> 5;
    const int lane = tid & 31;
    const int b    = blockIdx.x;
    const int u0   = b * UPB;

    // warp row assignments (3 rows/warp; 3|12 so never crosses a gate boundary)
    const int l0   = 3 * w;                   // 0..45
    const int gate = l0 / UPB;
    const int j0   = l0 % UPB;
    const int grow = gate * HH + u0 + j0;
    const __nv_bfloat16* w2base = g_w2cat + (size_t)grow * (2 * HH);
    const int r1row = b * RPB + l0;
    const __nv_bfloat16* w1base = g_whh1 + (size_t)r1row * HH;
    const float bsum0 = __ldg(&bih2[grow])     + __ldg(&bhh2[grow]);
    const float bsum1 = __ldg(&bih2[grow + 1]) + __ldg(&bhh2[grow + 1]);
    const float bsum2 = __ldg(&bih2[grow + 2]) + __ldg(&bhh2[grow + 2]);

    // ---- epoch base (flags monotonic across graph replays) ----
    if (tid == 0) sBase = g_flags[b * FSTR];
    __syncthreads();
    const unsigned base = sBase;

    // ======== PROLOGUE (distributed by block) ========
    if (tid < UPB) { g_c2[u0 + tid] = 0.f; g_h2[0][u0 + tid] = 0.f; }

    // (1) W_hh1: pure linear copy-convert (dst contiguous), 64B/iter
    {
        const unsigned nelem = RPB * HH;                 // 73728 floats
        const float* src = Whh1f + (size_t)b * RPB * HH;
        __nv_bfloat16* dst = g_whh1 + (size_t)b * RPB * HH;
        for (unsigned i = tid * 16u; i < nelem; i += NT * 16u) {
            float4 a0 = __ldg((const float4*)(src + i));
            float4 a1 = __ldg((const float4*)(src + i + 4));
            float4 a2 = __ldg((const float4*)(src + i + 8));
            float4 a3 = __ldg((const float4*)(src + i + 12));
            *(uint4*)(dst + i)     = cvt8(a0, a1);
            *(uint4*)(dst + i + 8) = cvt8(a2, a3);
        }
    }
    // (2) W_ih2 / W_hh2 -> concat layout; 32-bit index math, 64B/iter
    {
        const unsigned r0 = (unsigned)b * RPB;
        #pragma unroll
        for (int m = 0; m < 2; m++) {
            const float* src = (m == 0) ? Wih2f : Whh2f;
            const unsigned coloff = (m == 0) ? 0u : (unsigned)HH;
            // RPB*HH/16 = 4608 chunks of 16 floats; HH/16 = 96 chunks/row
            for (unsigned i = tid; i < RPB * HH / 16; i += NT) {
                unsigned row = i / 96u;
                unsigned col = (i - row * 96u) * 16u;
                const float* s = src + (size_t)(r0 + row) * HH + col;
                float4 a0 = __ldg((const float4*)s);
                float4 a1 = __ldg((const float4*)(s + 4));
                float4 a2 = __ldg((const float4*)(s + 8));
                float4 a3 = __ldg((const float4*)(s + 12));
                __nv_bfloat16* d = g_w2cat + (size_t)(r0 + row) * (2 * HH) + coloff + col;
                *(uint4*)d       = cvt8(a0, a1);
                *(uint4*)(d + 8) = cvt8(a2, a3);
            }
        }
    }

    // xproj: own rows r, r+1, r+2 (per warp) for all 128 embeddings
    {
        const int r = b * RPB + w * 3;
        u64 wa[8], wb[8], wc[8];
        {
            const float4* wra = (const float4*)(Wih1 + (size_t)r * E);
            const float4* wrb = (const float4*)(Wih1 + (size_t)(r + 1) * E);
            const float4* wrc = (const float4*)(Wih1 + (size_t)(r + 2) * E);
            #pragma unroll
            for (int i = 0; i < 4; i++) {
                float4 A = __ldg(&wra[lane * 4 + i]);
                float4 B = __ldg(&wrb[lane * 4 + i]);
                float4 C = __ldg(&wrc[lane * 4 + i]);
                wa[2 * i] = f2pack(A.x, A.y); wa[2 * i + 1] = f2pack(A.z, A.w);
                wb[2 * i] = f2pack(B.x, B.y); wb[2 * i + 1] = f2pack(B.z, B.w);
                wc[2 * i] = f2pack(C.x, C.y); wc[2 * i + 1] = f2pack(C.z, C.w);
            }
        }
        const float bs0 = __ldg(&bih1[r])     + __ldg(&bhh1[r]);
        const float bs1 = __ldg(&bih1[r + 1]) + __ldg(&bhh1[r + 1]);
        const float bs2 = __ldg(&bih1[r + 2]) + __ldg(&bhh1[r + 2]);

        for (int c = 0; c < NV / 16; c++) {
            __syncthreads();
            for (int idx = tid; idx < 16 * (E / 4); idx += NT) {
                int v = idx >> 7, e4 = idx & 127;
                float4 d = __ldg((const float4*)(emb + (size_t)(c * 16 + v) * E) + e4);
                *(float4*)&sMem[v * (E + 8) + e4 * 4] = d;
            }
            __syncthreads();
            #pragma unroll 2
            for (int v = 0; v < 16; v++) {
                const float* ev = &sMem[v * (E + 8) + lane * 16];
                u64 s0 = 0ull, s1 = 0ull, s2 = 0ull;
                #pragma unroll
                for (int i = 0; i < 4; i++) {
                    float4 x = *(const float4*)(ev + 4 * i);
                    u64 x0 = f2pack(x.x, x.y), x1 = f2pack(x.z, x.w);
                    s0 = ffma2(wa[2 * i], x0, s0);
                    s0 = ffma2(wa[2 * i + 1], x1, s0);
                    s1 = ffma2(wb[2 * i], x0, s1);
                    s1 = ffma2(wb[2 * i + 1], x1, s1);
                    s2 = ffma2(wc[2 * i], x0, s2);
                    s2 = ffma2(wc[2 * i + 1], x1, s2);
                }
                float a0 = warpsum(f2sum(s0));
                float a1 = warpsum(f2sum(s1));
                float a2 = warpsum(f2sum(s2));
                if (lane == 0) {
                    size_t o = (size_t)(c * 16 + v) * G4 + r;
                    g_xproj[o]     = a0 + bs0;
                    g_xproj[o + 1] = a1 + bs1;
                    g_xproj[o + 2] = a2 + bs2;
                }
            }
        }
    }

    grid_sync(b, base + 1);

    // ======== 48-step controller loop ========
    for (int t = 0; t < TT; t++) {
        const int par = t & 1;
        const int rb = t % 3, wb2 = (t + 1) % 3, zb = (t + 2) % 3;

        // ---- loads: logits FIRST (softmax gates the chain) ----
        float lg = 0.f;
        if (t > 0) lg = g_log3[rb][lane * LSTR] + bout[(t - 1) * SS + lane];
        float a0[KU], a1[KU], a2[KU], a3[KU], cc[KU];
        #pragma unroll
        for (int k = 0; k < KU; k++) {
            int u = tid + k * NT;
            sV[HH + u] = g_h2[par][u];          // stage h2(t-1)
            if (t > 0) {
                a0[k] = g_g1[par][u];          a1[k] = g_g1[par][HH + u];
                a2[k] = g_g1[par][2 * HH + u]; a3[k] = g_g1[par][3 * HH + u];
                cc[k] = g_c1[par][u];
            } else {
                a0[k] = a1[k] = a2[k] = a3[k] = cc[k] = 0.f;
            }
        }
        if (tid < SS * UPB) {   // fp32 head slice for this block's units
            int s = tid / UPB, j = tid % UPB;
            sWo[tid] = __ldg(&Wout[((size_t)t * SS + s) * HH + u0 + j]);
        }

        // ---- per-warp redundant softmax/argmax of step t-1 (shfl-only) ----
        int sid;
        if (t > 0) {
            float v = lg;
            float bv = v; int bi = lane;
            #pragma unroll
            for (int o = 16; o; o >>= 1) {
                float ov = __shfl_xor_sync(0xffffffffu, bv, o);
                int   oi = __shfl_xor_sync(0xffffffffu, bi, o);
                if (ov > bv || (ov == bv && oi < bi)) { bv = ov; bi = oi; }
            }
            float e = expf(v - bv), se = e;
            #pragma unroll
            for (int o = 16; o; o >>= 1) se += __shfl_xor_sync(0xffffffffu, se, o);
            float lse = bv + logf(se);
            if (b == 0 && w == 0) out[(t - 1) * SS + lane] = v - lse;
            sid = ((t - 1) & 3) * SS + bi;
        } else {
            sid = *input_id;
        }

        // ---- xproj prefetch, then h1 build ----
        {
            const float* xp = g_xproj + (size_t)sid * G4;
            float xg0[KU], xg1[KU], xg2[KU], xg3[KU];
            #pragma unroll
            for (int k = 0; k < KU; k++) {
                int u = tid + k * NT;
                xg0[k] = __ldg(&xp[u]);
                xg1[k] = __ldg(&xp[HH + u]);
                xg2[k] = __ldg(&xp[2 * HH + u]);
                xg3[k] = __ldg(&xp[3 * HH + u]);
            }
            #pragma unroll
            for (int k = 0; k < KU; k++) {
                int u = tid + k * NT;
                float gi = a0[k] + xg0[k];
                float gf = a1[k] + xg1[k];
                float gg = a2[k] + xg2[k];
                float go = a3[k] + xg3[k];
                float cn = fsigm(gf) * cc[k] + fsigm(gi) * ftanh(gg);
                sV[u] = fsigm(go) * ftanh(cn);
                if (u >= u0 && u < u0 + UPB) g_c1[par ^ 1][u] = cn;
            }
        }
        __syncthreads();   // h1 + h2 staged

        // ---- dotA: W_hh2 @ h2(t-1) ----
        float acc[3] = {0.f, 0.f, 0.f};
        dot3_acc<6>(w2base + HH, 2 * HH, sV + HH, lane, acc);

        // ---- FUSED dotB: W_ih2 rows + W_hh1 rows, one pass over h1(t) ----
        float r1[3] = {0.f, 0.f, 0.f};
        dot3x3_acc<6>(w2base, 2 * HH, w1base, HH, sV, lane, acc, r1);
        acc[0] = warpsum(acc[0]);
        acc[1] = warpsum(acc[1]);
        acc[2] = warpsum(acc[2]);
        r1[0]  = warpsum(r1[0]);
        r1[1]  = warpsum(r1[1]);
        r1[2]  = warpsum(r1[2]);
        if (lane == 0) {
            sG[l0]     = acc[0] + bsum0;
            sG[l0 + 1] = acc[1] + bsum1;
            sG[l0 + 2] = acc[2] + bsum2;
            g_g1[par ^ 1][r1row]     = r1[0];
            g_g1[par ^ 1][r1row + 1] = r1[1];
            g_g1[par ^ 1][r1row + 2] = r1[2];
        }
        __syncthreads();

        // ---- finalize own h2 units + partial logits -> spread atomics ----
        if (w == 0) {
            float hn = 0.f;
            if (lane < UPB) {
                int u = u0 + lane;
                float gi = sG[lane],           gf = sG[UPB + lane];
                float gg = sG[2 * UPB + lane], go = sG[3 * UPB + lane];
                float c  = g_c2[u];
                float cn = fsigm(gf) * c + fsigm(gi) * ftanh(gg);
                g_c2[u]          = cn;
                hn               = fsigm(go) * ftanh(cn);
                g_h2[par ^ 1][u] = hn;
            }
            float p = 0.f;
            #pragma unroll
            for (int j = 0; j < UPB; j++) {
                float hj = __shfl_sync(0xffffffffu, hn, j);
                p = fmaf(sWo[lane * UPB + j], hj, p);
            }
            atomicAdd(&g_log3[wb2][lane * LSTR], p);
        }
        if (b == 0 && w == 1) g_log3[zb][lane * LSTR] = 0.0f;  // recycle buffer

        grid_sync(b, base + 2 + (unsigned)t);
    }

    // epilogue: logp(47) from g_log3[48%3 = 0]
    if (b == 0 && w == 0) {
        float v = g_log3[0][lane * LSTR] + bout[47 * SS + lane];
        float m = v;
        #pragma unroll
        for (int o = 16; o; o >>= 1) m = fmaxf(m, __shfl_xor_sync(0xffffffffu, m, o));
        float e = expf(v - m), se = e;
        #pragma unroll
        for (int o = 16; o; o >>= 1) se += __shfl_xor_sync(0xffffffffu, se, o);
        float lse = m + logf(se);
        out[47 * SS + lane] = v - lse;
    }
}

extern "C" void kernel_launch(void* const* d_in, const int* in_sizes, int n_in,
                              void* d_out, int out_size) {
    const int*   input_id = (const int*)  d_in[0];
    const float* emb      = (const float*)d_in[1];
    const float* W_ih1    = (const float*)d_in[2];
    const float* W_hh1    = (const float*)d_in[3];
    const float* b_ih1    = (const float*)d_in[4];
    const float* b_hh1    = (const float*)d_in[5];
    const float* W_ih2    = (const float*)d_in[6];
    const float* W_hh2    = (const float*)d_in[7];
    const float* b_ih2    = (const float*)d_in[8];
    const float* b_hh2    = (const float*)d_in[9];
    const float* W_out    = (const float*)d_in[10];
    const float* b_out    = (const float*)d_in[11];
    float* out = (float*)d_out;

    nas_all<<<NB, NT>>>(input_id, emb, W_ih1, W_hh1, b_ih1, b_hh1,
                        W_ih2, W_hh2, b_ih2, b_hh2, W_out, b_out, out);
}